// round 6
// baseline (speedup 1.0000x reference)
#include <cuda_runtime.h>

// ---------------------------------------------------------------------------
// Fused 2-layer LSTM (H=50, D=1) + FC, B=2048, T=512, fp32.
//
// R6 design (vs R5):
//  * Weights no longer in shared memory. A prepack kernel writes them into
//    __device__ global scratch in a k-paired, gate-interleaved layout; the
//    main kernel reads them with LDG.128 (L1-resident, sector-dedup across
//    lanes sharing a hid). This removes 2/3 of the smem crossbar bytes that
//    bound R5 (l1tex 86%).
//  * Gate pre-activations accumulate with packed fma.rn.f32x2 over k-pairs:
//    P += (w_k, w_{k+1}) * (h_k, h_{k+1}); horizontal add once per gate.
//    Halves FFMA-pipe load with no operand-duplication MOVs.
//  * h kept in smem, batch-major rows padded to 58 floats (bank-clean for
//    the 7 batch-pair strides), read as 8-byte (h_k,h_{k+1}) words.
// ---------------------------------------------------------------------------

#define HN      50
#define KP      25            // k-pairs
#define TN      512
#define BATCHN  2048
#define NB      14            // batches per block
#define NPAIR   7             // batch pairs per block
#define NTHREADS (NPAIR * HN) // 350
#define NGRID   147           // 147*14 = 2058 >= 2048
#define HROW    58            // padded h row (floats); 2*HROW*pr distinct mod 32

typedef unsigned long long u64;

// Prepacked weights (device scratch; written by prepack_kernel each launch).
// g_wp0: layer-0 recurrent, float idx = (kp*HN+hid)*8 + gate*2 + j
//        -> per (kp,hid): [i0,i1, f0,f1, g0,g1, o0,o1]
// g_wp1: layer-1, float idx = (kp*HN+hid)*16 + m*8 + gate*2 + j  (m=0:Wih1, 1:Whh1)
__device__ float4 g_wp0[KP * HN * 2];
__device__ float4 g_wp1[KP * HN * 4];

__device__ __forceinline__ void fma2(u64& d, u64 a, u64 b) {
    asm("fma.rn.f32x2 %0, %1, %2, %0;" : "+l"(d) : "l"(a), "l"(b));
}
__device__ __forceinline__ float hsum2(u64 v) {
    float lo, hi;
    asm("mov.b64 {%0, %1}, %2;" : "=f"(lo), "=f"(hi) : "l"(v));
    return lo + hi;
}
__device__ __forceinline__ float sig_f(float v) {
    return __fdividef(1.0f, 1.0f + __expf(-v));
}
__device__ __forceinline__ float tanh_f(float v) {
    return 1.0f - __fdividef(2.0f, 1.0f + __expf(2.0f * v));
}

__global__ void prepack_kernel(const float* __restrict__ Whh0,
                               const float* __restrict__ Wih1,
                               const float* __restrict__ Whh1)
{
    const int i = blockIdx.x * blockDim.x + threadIdx.x;
    if (i < KP * HN * 8) {
        const int j = i & 1, g = (i >> 1) & 3;
        const int hid = (i >> 3) % HN, kp = (i >> 3) / HN;
        reinterpret_cast<float*>(g_wp0)[i] = Whh0[(g * HN + hid) * HN + 2 * kp + j];
    }
    if (i < KP * HN * 16) {
        const int j = i & 1, g = (i >> 1) & 3, m = (i >> 3) & 1;
        const int hid = (i >> 4) % HN, kp = (i >> 4) / HN;
        const float* W = m ? Whh1 : Wih1;
        reinterpret_cast<float*>(g_wp1)[i] = W[(g * HN + hid) * HN + 2 * kp + j];
    }
}

__global__ __launch_bounds__(NTHREADS, 1)
void lstm_fused_kernel(const float* __restrict__ x,      // [B,T,1]
                       const float* __restrict__ Wih0,   // [200,1]
                       const float* __restrict__ bih0,   // [200]
                       const float* __restrict__ bhh0,   // [200]
                       const float* __restrict__ bih1,   // [200]
                       const float* __restrict__ bhh1,   // [200]
                       const float* __restrict__ Wfc,    // [2,50]
                       const float* __restrict__ bfc,    // [2]
                       float* __restrict__ out)          // [B,2]
{
    __shared__ float h0s[2][NB][HROW];     // layer-0 hidden, batch-major
    __shared__ float h1s[2][NB][HROW];     // layer-1 hidden, batch-major
    __shared__ float4 bias0s[HN], bias1s[HN], wx0s[HN];
    __shared__ float wfc_s[2 * HN];
    __shared__ float bfc_s[2];

    const int tid = threadIdx.x;

    // ------- stage biases / x-weights / fc into shared -------
    for (int hid = tid; hid < HN; hid += NTHREADS) {
        bias0s[hid] = make_float4(bih0[0 * HN + hid] + bhh0[0 * HN + hid],
                                  bih0[1 * HN + hid] + bhh0[1 * HN + hid],
                                  bih0[2 * HN + hid] + bhh0[2 * HN + hid],
                                  bih0[3 * HN + hid] + bhh0[3 * HN + hid]);
        bias1s[hid] = make_float4(bih1[0 * HN + hid] + bhh1[0 * HN + hid],
                                  bih1[1 * HN + hid] + bhh1[1 * HN + hid],
                                  bih1[2 * HN + hid] + bhh1[2 * HN + hid],
                                  bih1[3 * HN + hid] + bhh1[3 * HN + hid]);
        wx0s[hid] = make_float4(Wih0[0 * HN + hid], Wih0[1 * HN + hid],
                                Wih0[2 * HN + hid], Wih0[3 * HN + hid]);
    }
    for (int i = tid; i < 2 * HN; i += NTHREADS) wfc_s[i] = Wfc[i];
    if (tid < 2) bfc_s[tid] = bfc[tid];
    // zero initial hidden state (buffer 0 read at t=0)
    for (int i = tid; i < NB * HROW; i += NTHREADS) {
        (&h0s[0][0][0])[i] = 0.0f;
        (&h1s[0][0][0])[i] = 0.0f;
    }
    __syncthreads();

    // ------- per-thread identity -------
    const int hid = tid / NPAIR;
    const int pr  = tid % NPAIR;
    const int lb0 = pr * 2, lb1 = lb0 + 1;          // local batches
    const int b0  = blockIdx.x * NB + lb0;
    const int b1  = b0 + 1;
    const long xo0 = (long)(b0 < BATCHN ? b0 : BATCHN - 1) * TN;
    const long xo1 = (long)(b1 < BATCHN ? b1 : BATCHN - 1) * TN;

    const float4 bi0 = bias0s[hid];
    const float4 bi1 = bias1s[hid];
    const float4 wx  = wx0s[hid];

    // weight base pointers (k-pair slabs strided by HN entries)
    const ulonglong2* __restrict__ w0p =
        reinterpret_cast<const ulonglong2*>(g_wp0) + hid * 2;
    const ulonglong2* __restrict__ w1p =
        reinterpret_cast<const ulonglong2*>(g_wp1) + hid * 4;

    float c00 = 0.0f, c01 = 0.0f;   // layer-0 cell state
    float c10 = 0.0f, c11 = 0.0f;   // layer-1 cell state

    float xa = x[xo0];
    float xb = x[xo1];

#pragma unroll 1
    for (int t = 0; t < TN; ++t) {
        const int rb = t & 1;
        const int wb = rb ^ 1;

        // prefetch next x
        const int tn = (t + 1 < TN) ? (t + 1) : (TN - 1);
        const float xan = x[xo0 + tn];
        const float xbn = x[xo1 + tn];

        // ---- layer 0: P_gate[batch] += (w_k,w_k1) * (h_k,h_k1), k-paired ----
        u64 Pia = 0, Pfa = 0, Pga = 0, Poa = 0;
        u64 Pib = 0, Pfb = 0, Pgb = 0, Pob = 0;
        {
            const u64* __restrict__ hap =
                reinterpret_cast<const u64*>(&h0s[rb][lb0][0]);
            const u64* __restrict__ hbp =
                reinterpret_cast<const u64*>(&h0s[rb][lb1][0]);
#pragma unroll
            for (int kp = 0; kp < KP; ++kp) {
                const ulonglong2 wif = w0p[kp * HN * 2];      // (i-pair, f-pair)
                const ulonglong2 wgo = w0p[kp * HN * 2 + 1];  // (g-pair, o-pair)
                const u64 ha = hap[kp];
                const u64 hb = hbp[kp];
                fma2(Pia, wif.x, ha); fma2(Pfa, wif.y, ha);
                fma2(Pga, wgo.x, ha); fma2(Poa, wgo.y, ha);
                fma2(Pib, wif.x, hb); fma2(Pfb, wif.y, hb);
                fma2(Pgb, wgo.x, hb); fma2(Pob, wgo.y, hb);
            }
        }
        float h0a, h0b;
        {
            const float Ai = hsum2(Pia) + __fmaf_rn(wx.x, xa, bi0.x);
            const float Af = hsum2(Pfa) + __fmaf_rn(wx.y, xa, bi0.y);
            const float Ag = hsum2(Pga) + __fmaf_rn(wx.z, xa, bi0.z);
            const float Ao = hsum2(Poa) + __fmaf_rn(wx.w, xa, bi0.w);
            const float i_ = sig_f(Ai), f_ = sig_f(Af);
            const float g_ = tanh_f(Ag), o_ = sig_f(Ao);
            c00 = f_ * c00 + i_ * g_;
            h0a = o_ * tanh_f(c00);
        }
        {
            const float Ai = hsum2(Pib) + __fmaf_rn(wx.x, xb, bi0.x);
            const float Af = hsum2(Pfb) + __fmaf_rn(wx.y, xb, bi0.y);
            const float Ag = hsum2(Pgb) + __fmaf_rn(wx.z, xb, bi0.z);
            const float Ao = hsum2(Pob) + __fmaf_rn(wx.w, xb, bi0.w);
            const float i_ = sig_f(Ai), f_ = sig_f(Af);
            const float g_ = tanh_f(Ag), o_ = sig_f(Ao);
            c01 = f_ * c01 + i_ * g_;
            h0b = o_ * tanh_f(c01);
        }
        h0s[wb][lb0][hid] = h0a;
        h0s[wb][lb1][hid] = h0b;
        __syncthreads();

        // ---- layer 1: gates += Wih1 @ h0_t + Whh1 @ h1_{t-1} ----
        u64 Qia = 0, Qfa = 0, Qga = 0, Qoa = 0;
        u64 Qib = 0, Qfb = 0, Qgb = 0, Qob = 0;
        {
            const u64* __restrict__ pap =
                reinterpret_cast<const u64*>(&h0s[wb][lb0][0]);
            const u64* __restrict__ pbp =
                reinterpret_cast<const u64*>(&h0s[wb][lb1][0]);
            const u64* __restrict__ qap =
                reinterpret_cast<const u64*>(&h1s[rb][lb0][0]);
            const u64* __restrict__ qbp =
                reinterpret_cast<const u64*>(&h1s[rb][lb1][0]);
#pragma unroll
            for (int kp = 0; kp < KP; ++kp) {
                const ulonglong2 wa0 = w1p[kp * HN * 4];      // Wih1 (i,f)
                const ulonglong2 wa1 = w1p[kp * HN * 4 + 1];  // Wih1 (g,o)
                const ulonglong2 wr0 = w1p[kp * HN * 4 + 2];  // Whh1 (i,f)
                const ulonglong2 wr1 = w1p[kp * HN * 4 + 3];  // Whh1 (g,o)
                const u64 pa = pap[kp];
                const u64 pb = pbp[kp];
                const u64 qa = qap[kp];
                const u64 qb = qbp[kp];
                fma2(Qia, wa0.x, pa); fma2(Qfa, wa0.y, pa);
                fma2(Qga, wa1.x, pa); fma2(Qoa, wa1.y, pa);
                fma2(Qia, wr0.x, qa); fma2(Qfa, wr0.y, qa);
                fma2(Qga, wr1.x, qa); fma2(Qoa, wr1.y, qa);
                fma2(Qib, wa0.x, pb); fma2(Qfb, wa0.y, pb);
                fma2(Qgb, wa1.x, pb); fma2(Qob, wa1.y, pb);
                fma2(Qib, wr0.x, qb); fma2(Qfb, wr0.y, qb);
                fma2(Qgb, wr1.x, qb); fma2(Qob, wr1.y, qb);
            }
        }
        float h1a, h1b;
        {
            const float Ai = hsum2(Qia) + bi1.x;
            const float Af = hsum2(Qfa) + bi1.y;
            const float Ag = hsum2(Qga) + bi1.z;
            const float Ao = hsum2(Qoa) + bi1.w;
            const float i_ = sig_f(Ai), f_ = sig_f(Af);
            const float g_ = tanh_f(Ag), o_ = sig_f(Ao);
            c10 = f_ * c10 + i_ * g_;
            h1a = o_ * tanh_f(c10);
        }
        {
            const float Ai = hsum2(Qib) + bi1.x;
            const float Af = hsum2(Qfb) + bi1.y;
            const float Ag = hsum2(Qgb) + bi1.z;
            const float Ao = hsum2(Qob) + bi1.w;
            const float i_ = sig_f(Ai), f_ = sig_f(Af);
            const float g_ = tanh_f(Ag), o_ = sig_f(Ao);
            c11 = f_ * c11 + i_ * g_;
            h1b = o_ * tanh_f(c11);
        }
        h1s[wb][lb0][hid] = h1a;
        h1s[wb][lb1][hid] = h1b;
        __syncthreads();

        xa = xan;
        xb = xbn;
    }

    // ---- final FC: out[b,c] = h1_last[b,:] . Wfc[c,:] + bfc[c] ----
    const int FB = TN & 1;   // buffer holding h1 at t=T-1 (=0 for even T)
    if (tid < NB * 2) {
        const int pb = tid >> 1;
        const int cc = tid & 1;
        const int b = blockIdx.x * NB + pb;
        if (b < BATCHN) {
            float acc = bfc_s[cc];
#pragma unroll
            for (int k = 0; k < HN; ++k)
                acc += h1s[FB][pb][k] * wfc_s[cc * HN + k];
            out[b * 2 + cc] = acc;
        }
    }
}

extern "C" void kernel_launch(void* const* d_in, const int* in_sizes, int n_in,
                              void* d_out, int out_size)
{
    (void)in_sizes; (void)n_in; (void)out_size;

    const float* x    = (const float*)d_in[0];
    const float* Wih0 = (const float*)d_in[1];
    const float* Whh0 = (const float*)d_in[2];
    const float* bih0 = (const float*)d_in[3];
    const float* bhh0 = (const float*)d_in[4];
    const float* Wih1 = (const float*)d_in[5];
    const float* Whh1 = (const float*)d_in[6];
    const float* bih1 = (const float*)d_in[7];
    const float* bhh1 = (const float*)d_in[8];
    const float* Wfc  = (const float*)d_in[9];
    const float* bfc  = (const float*)d_in[10];

    // Repack weights into __device__ scratch (k-paired, gate-interleaved).
    prepack_kernel<<<(KP * HN * 16 + 255) / 256, 256>>>(Whh0, Wih1, Whh1);

    lstm_fused_kernel<<<NGRID, NTHREADS>>>(
        x, Wih0, bih0, bhh0, bih1, bhh1, Wfc, bfc, (float*)d_out);
}

// round 8
// speedup vs baseline: 1.0042x; 1.0042x over previous
#include <cuda_runtime.h>

// ---------------------------------------------------------------------------
// Fused 2-layer LSTM (H=50, D=1) + FC, B=2048, T=512, fp32.
//
// R6 design (vs R5):
//  * Weights no longer in shared memory. A prepack kernel writes them into
//    __device__ global scratch in a k-paired, gate-interleaved layout; the
//    main kernel reads them with LDG.128 (L1-resident, sector-dedup across
//    lanes sharing a hid). This removes 2/3 of the smem crossbar bytes that
//    bound R5 (l1tex 86%).
//  * Gate pre-activations accumulate with packed fma.rn.f32x2 over k-pairs:
//    P += (w_k, w_{k+1}) * (h_k, h_{k+1}); horizontal add once per gate.
//    Halves FFMA-pipe load with no operand-duplication MOVs.
//  * h kept in smem, batch-major rows padded to 58 floats (bank-clean for
//    the 7 batch-pair strides), read as 8-byte (h_k,h_{k+1}) words.
// ---------------------------------------------------------------------------

#define HN      50
#define KP      25            // k-pairs
#define TN      512
#define BATCHN  2048
#define NB      14            // batches per block
#define NPAIR   7             // batch pairs per block
#define NTHREADS (NPAIR * HN) // 350
#define NGRID   147           // 147*14 = 2058 >= 2048
#define HROW    58            // padded h row (floats); 2*HROW*pr distinct mod 32

typedef unsigned long long u64;

// Prepacked weights (device scratch; written by prepack_kernel each launch).
// g_wp0: layer-0 recurrent, float idx = (kp*HN+hid)*8 + gate*2 + j
//        -> per (kp,hid): [i0,i1, f0,f1, g0,g1, o0,o1]
// g_wp1: layer-1, float idx = (kp*HN+hid)*16 + m*8 + gate*2 + j  (m=0:Wih1, 1:Whh1)
__device__ float4 g_wp0[KP * HN * 2];
__device__ float4 g_wp1[KP * HN * 4];

__device__ __forceinline__ void fma2(u64& d, u64 a, u64 b) {
    asm("fma.rn.f32x2 %0, %1, %2, %0;" : "+l"(d) : "l"(a), "l"(b));
}
__device__ __forceinline__ float hsum2(u64 v) {
    float lo, hi;
    asm("mov.b64 {%0, %1}, %2;" : "=f"(lo), "=f"(hi) : "l"(v));
    return lo + hi;
}
__device__ __forceinline__ float sig_f(float v) {
    return __fdividef(1.0f, 1.0f + __expf(-v));
}
__device__ __forceinline__ float tanh_f(float v) {
    return 1.0f - __fdividef(2.0f, 1.0f + __expf(2.0f * v));
}

__global__ void prepack_kernel(const float* __restrict__ Whh0,
                               const float* __restrict__ Wih1,
                               const float* __restrict__ Whh1)
{
    const int i = blockIdx.x * blockDim.x + threadIdx.x;
    if (i < KP * HN * 8) {
        const int j = i & 1, g = (i >> 1) & 3;
        const int hid = (i >> 3) % HN, kp = (i >> 3) / HN;
        reinterpret_cast<float*>(g_wp0)[i] = Whh0[(g * HN + hid) * HN + 2 * kp + j];
    }
    if (i < KP * HN * 16) {
        const int j = i & 1, g = (i >> 1) & 3, m = (i >> 3) & 1;
        const int hid = (i >> 4) % HN, kp = (i >> 4) / HN;
        const float* W = m ? Whh1 : Wih1;
        reinterpret_cast<float*>(g_wp1)[i] = W[(g * HN + hid) * HN + 2 * kp + j];
    }
}

__global__ __launch_bounds__(NTHREADS, 1)
void lstm_fused_kernel(const float* __restrict__ x,      // [B,T,1]
                       const float* __restrict__ Wih0,   // [200,1]
                       const float* __restrict__ bih0,   // [200]
                       const float* __restrict__ bhh0,   // [200]
                       const float* __restrict__ bih1,   // [200]
                       const float* __restrict__ bhh1,   // [200]
                       const float* __restrict__ Wfc,    // [2,50]
                       const float* __restrict__ bfc,    // [2]
                       float* __restrict__ out)          // [B,2]
{
    __shared__ float h0s[2][NB][HROW];     // layer-0 hidden, batch-major
    __shared__ float h1s[2][NB][HROW];     // layer-1 hidden, batch-major
    __shared__ float4 bias0s[HN], bias1s[HN], wx0s[HN];
    __shared__ float wfc_s[2 * HN];
    __shared__ float bfc_s[2];

    const int tid = threadIdx.x;

    // ------- stage biases / x-weights / fc into shared -------
    for (int hid = tid; hid < HN; hid += NTHREADS) {
        bias0s[hid] = make_float4(bih0[0 * HN + hid] + bhh0[0 * HN + hid],
                                  bih0[1 * HN + hid] + bhh0[1 * HN + hid],
                                  bih0[2 * HN + hid] + bhh0[2 * HN + hid],
                                  bih0[3 * HN + hid] + bhh0[3 * HN + hid]);
        bias1s[hid] = make_float4(bih1[0 * HN + hid] + bhh1[0 * HN + hid],
                                  bih1[1 * HN + hid] + bhh1[1 * HN + hid],
                                  bih1[2 * HN + hid] + bhh1[2 * HN + hid],
                                  bih1[3 * HN + hid] + bhh1[3 * HN + hid]);
        wx0s[hid] = make_float4(Wih0[0 * HN + hid], Wih0[1 * HN + hid],
                                Wih0[2 * HN + hid], Wih0[3 * HN + hid]);
    }
    for (int i = tid; i < 2 * HN; i += NTHREADS) wfc_s[i] = Wfc[i];
    if (tid < 2) bfc_s[tid] = bfc[tid];
    // zero initial hidden state (buffer 0 read at t=0)
    for (int i = tid; i < NB * HROW; i += NTHREADS) {
        (&h0s[0][0][0])[i] = 0.0f;
        (&h1s[0][0][0])[i] = 0.0f;
    }
    __syncthreads();

    // ------- per-thread identity -------
    const int hid = tid / NPAIR;
    const int pr  = tid % NPAIR;
    const int lb0 = pr * 2, lb1 = lb0 + 1;          // local batches
    const int b0  = blockIdx.x * NB + lb0;
    const int b1  = b0 + 1;
    const long xo0 = (long)(b0 < BATCHN ? b0 : BATCHN - 1) * TN;
    const long xo1 = (long)(b1 < BATCHN ? b1 : BATCHN - 1) * TN;

    const float4 bi0 = bias0s[hid];
    const float4 bi1 = bias1s[hid];
    const float4 wx  = wx0s[hid];

    // weight base pointers (k-pair slabs strided by HN entries)
    const ulonglong2* __restrict__ w0p =
        reinterpret_cast<const ulonglong2*>(g_wp0) + hid * 2;
    const ulonglong2* __restrict__ w1p =
        reinterpret_cast<const ulonglong2*>(g_wp1) + hid * 4;

    float c00 = 0.0f, c01 = 0.0f;   // layer-0 cell state
    float c10 = 0.0f, c11 = 0.0f;   // layer-1 cell state

    float xa = x[xo0];
    float xb = x[xo1];

#pragma unroll 1
    for (int t = 0; t < TN; ++t) {
        const int rb = t & 1;
        const int wb = rb ^ 1;

        // prefetch next x
        const int tn = (t + 1 < TN) ? (t + 1) : (TN - 1);
        const float xan = x[xo0 + tn];
        const float xbn = x[xo1 + tn];

        // ---- layer 0: P_gate[batch] += (w_k,w_k1) * (h_k,h_k1), k-paired ----
        u64 Pia = 0, Pfa = 0, Pga = 0, Poa = 0;
        u64 Pib = 0, Pfb = 0, Pgb = 0, Pob = 0;
        {
            const u64* __restrict__ hap =
                reinterpret_cast<const u64*>(&h0s[rb][lb0][0]);
            const u64* __restrict__ hbp =
                reinterpret_cast<const u64*>(&h0s[rb][lb1][0]);
#pragma unroll
            for (int kp = 0; kp < KP; ++kp) {
                const ulonglong2 wif = w0p[kp * HN * 2];      // (i-pair, f-pair)
                const ulonglong2 wgo = w0p[kp * HN * 2 + 1];  // (g-pair, o-pair)
                const u64 ha = hap[kp];
                const u64 hb = hbp[kp];
                fma2(Pia, wif.x, ha); fma2(Pfa, wif.y, ha);
                fma2(Pga, wgo.x, ha); fma2(Poa, wgo.y, ha);
                fma2(Pib, wif.x, hb); fma2(Pfb, wif.y, hb);
                fma2(Pgb, wgo.x, hb); fma2(Pob, wgo.y, hb);
            }
        }
        float h0a, h0b;
        {
            const float Ai = hsum2(Pia) + __fmaf_rn(wx.x, xa, bi0.x);
            const float Af = hsum2(Pfa) + __fmaf_rn(wx.y, xa, bi0.y);
            const float Ag = hsum2(Pga) + __fmaf_rn(wx.z, xa, bi0.z);
            const float Ao = hsum2(Poa) + __fmaf_rn(wx.w, xa, bi0.w);
            const float i_ = sig_f(Ai), f_ = sig_f(Af);
            const float g_ = tanh_f(Ag), o_ = sig_f(Ao);
            c00 = f_ * c00 + i_ * g_;
            h0a = o_ * tanh_f(c00);
        }
        {
            const float Ai = hsum2(Pib) + __fmaf_rn(wx.x, xb, bi0.x);
            const float Af = hsum2(Pfb) + __fmaf_rn(wx.y, xb, bi0.y);
            const float Ag = hsum2(Pgb) + __fmaf_rn(wx.z, xb, bi0.z);
            const float Ao = hsum2(Pob) + __fmaf_rn(wx.w, xb, bi0.w);
            const float i_ = sig_f(Ai), f_ = sig_f(Af);
            const float g_ = tanh_f(Ag), o_ = sig_f(Ao);
            c01 = f_ * c01 + i_ * g_;
            h0b = o_ * tanh_f(c01);
        }
        h0s[wb][lb0][hid] = h0a;
        h0s[wb][lb1][hid] = h0b;
        __syncthreads();

        // ---- layer 1: gates += Wih1 @ h0_t + Whh1 @ h1_{t-1} ----
        u64 Qia = 0, Qfa = 0, Qga = 0, Qoa = 0;
        u64 Qib = 0, Qfb = 0, Qgb = 0, Qob = 0;
        {
            const u64* __restrict__ pap =
                reinterpret_cast<const u64*>(&h0s[wb][lb0][0]);
            const u64* __restrict__ pbp =
                reinterpret_cast<const u64*>(&h0s[wb][lb1][0]);
            const u64* __restrict__ qap =
                reinterpret_cast<const u64*>(&h1s[rb][lb0][0]);
            const u64* __restrict__ qbp =
                reinterpret_cast<const u64*>(&h1s[rb][lb1][0]);
#pragma unroll
            for (int kp = 0; kp < KP; ++kp) {
                const ulonglong2 wa0 = w1p[kp * HN * 4];      // Wih1 (i,f)
                const ulonglong2 wa1 = w1p[kp * HN * 4 + 1];  // Wih1 (g,o)
                const ulonglong2 wr0 = w1p[kp * HN * 4 + 2];  // Whh1 (i,f)
                const ulonglong2 wr1 = w1p[kp * HN * 4 + 3];  // Whh1 (g,o)
                const u64 pa = pap[kp];
                const u64 pb = pbp[kp];
                const u64 qa = qap[kp];
                const u64 qb = qbp[kp];
                fma2(Qia, wa0.x, pa); fma2(Qfa, wa0.y, pa);
                fma2(Qga, wa1.x, pa); fma2(Qoa, wa1.y, pa);
                fma2(Qia, wr0.x, qa); fma2(Qfa, wr0.y, qa);
                fma2(Qga, wr1.x, qa); fma2(Qoa, wr1.y, qa);
                fma2(Qib, wa0.x, pb); fma2(Qfb, wa0.y, pb);
                fma2(Qgb, wa1.x, pb); fma2(Qob, wa1.y, pb);
                fma2(Qib, wr0.x, qb); fma2(Qfb, wr0.y, qb);
                fma2(Qgb, wr1.x, qb); fma2(Qob, wr1.y, qb);
            }
        }
        float h1a, h1b;
        {
            const float Ai = hsum2(Qia) + bi1.x;
            const float Af = hsum2(Qfa) + bi1.y;
            const float Ag = hsum2(Qga) + bi1.z;
            const float Ao = hsum2(Qoa) + bi1.w;
            const float i_ = sig_f(Ai), f_ = sig_f(Af);
            const float g_ = tanh_f(Ag), o_ = sig_f(Ao);
            c10 = f_ * c10 + i_ * g_;
            h1a = o_ * tanh_f(c10);
        }
        {
            const float Ai = hsum2(Qib) + bi1.x;
            const float Af = hsum2(Qfb) + bi1.y;
            const float Ag = hsum2(Qgb) + bi1.z;
            const float Ao = hsum2(Qob) + bi1.w;
            const float i_ = sig_f(Ai), f_ = sig_f(Af);
            const float g_ = tanh_f(Ag), o_ = sig_f(Ao);
            c11 = f_ * c11 + i_ * g_;
            h1b = o_ * tanh_f(c11);
        }
        h1s[wb][lb0][hid] = h1a;
        h1s[wb][lb1][hid] = h1b;
        __syncthreads();

        xa = xan;
        xb = xbn;
    }

    // ---- final FC: out[b,c] = h1_last[b,:] . Wfc[c,:] + bfc[c] ----
    const int FB = TN & 1;   // buffer holding h1 at t=T-1 (=0 for even T)
    if (tid < NB * 2) {
        const int pb = tid >> 1;
        const int cc = tid & 1;
        const int b = blockIdx.x * NB + pb;
        if (b < BATCHN) {
            float acc = bfc_s[cc];
#pragma unroll
            for (int k = 0; k < HN; ++k)
                acc += h1s[FB][pb][k] * wfc_s[cc * HN + k];
            out[b * 2 + cc] = acc;
        }
    }
}

extern "C" void kernel_launch(void* const* d_in, const int* in_sizes, int n_in,
                              void* d_out, int out_size)
{
    (void)in_sizes; (void)n_in; (void)out_size;

    const float* x    = (const float*)d_in[0];
    const float* Wih0 = (const float*)d_in[1];
    const float* Whh0 = (const float*)d_in[2];
    const float* bih0 = (const float*)d_in[3];
    const float* bhh0 = (const float*)d_in[4];
    const float* Wih1 = (const float*)d_in[5];
    const float* Whh1 = (const float*)d_in[6];
    const float* bih1 = (const float*)d_in[7];
    const float* bhh1 = (const float*)d_in[8];
    const float* Wfc  = (const float*)d_in[9];
    const float* bfc  = (const float*)d_in[10];

    // Repack weights into __device__ scratch (k-paired, gate-interleaved).
    prepack_kernel<<<(KP * HN * 16 + 255) / 256, 256>>>(Whh0, Wih1, Whh1);

    lstm_fused_kernel<<<NGRID, NTHREADS>>>(
        x, Wih0, bih0, bhh0, bih1, bhh1, Wfc, bfc, (float*)d_out);
}